// round 2
// baseline (speedup 1.0000x reference)
#include <cuda_runtime.h>
#include <cuda_bf16.h>

#define B_    32
#define T_    2000
#define F_    80
#define H_    256
#define S_    100
#define D_    512        // 2*H
#define M_    (B_*T_)    // 64000
#define N2_   2048       // 2 dirs * 4H

// ------------------- scratch (static __device__, no allocs) -------------------
__device__ float g_col[(size_t)M_*768];          // im2col buffer (reused)
__device__ float g_x1 [(size_t)M_*256];          // conv1 out
__device__ float g_x2 [(size_t)M_*256];          // conv2 out
__device__ float g_gproj[(size_t)M_*N2_];        // input projections (reused L0/L1)
__device__ float g_hout0[(size_t)M_*D_];         // layer0 bilstm out
__device__ float g_hout1[(size_t)M_*D_];         // layer1 bilstm out
__device__ float g_w1t [240*256];
__device__ float g_w2t [768*256];
__device__ float g_wih0t[256*N2_];
__device__ float g_wih1t[512*N2_];
__device__ float g_wseg1t[D_*D_];
__device__ float g_wutt1t[D_*D_];
__device__ float g_pooled[B_*D_];
__device__ float g_hstate[2][2][H_*B_];          // [buf][dir][k*32+b]
__device__ unsigned g_bar;

// ------------------- small prep kernels -------------------
__global__ void k_tr_conv(const float* __restrict__ w, float* __restrict__ wt,
                          int Ci, int Co) {
    int i = blockIdx.x * blockDim.x + threadIdx.x;
    int tot = Co * Ci * 3;
    if (i < tot) {
        int k = i % 3;
        int ci = (i / 3) % Ci;
        int co = i / (3 * Ci);
        wt[(k * Ci + ci) * Co + co] = w[i];
    }
}

__global__ void k_tr_wih(const float* __restrict__ w, float* __restrict__ wt, int K) {
    int i = blockIdx.x * blockDim.x + threadIdx.x;   // i = dr*K + k
    int tot = 2048 * K;
    if (i < tot) {
        int k  = i % K;
        int dr = i / K;        // d*1024 + r
        wt[(size_t)k * 2048 + dr] = w[i];
    }
}

__global__ void k_tr_sq(const float* __restrict__ w, float* __restrict__ wt) {
    int i = blockIdx.x * blockDim.x + threadIdx.x;   // over 512*512
    if (i < D_ * D_) {
        int d = i / D_, k = i % D_;
        wt[k * D_ + d] = w[i];
    }
}

__global__ void k_zero(float* __restrict__ p, size_t n4) {
    size_t i = (size_t)blockIdx.x * blockDim.x + threadIdx.x;
    size_t stride = (size_t)gridDim.x * blockDim.x;
    float4 z = make_float4(0.f, 0.f, 0.f, 0.f);
    for (; i < n4; i += stride) ((float4*)p)[i] = z;
}

__global__ void k_scan_init() {
    int i = blockIdx.x * blockDim.x + threadIdx.x;
    if (i == 0) g_bar = 0u;
    float* p = &g_hstate[0][0][0];
    for (int j = i; j < 2 * 2 * H_ * B_; j += gridDim.x * blockDim.x) p[j] = 0.f;
}

// ------------------- im2col (pad=1, kernel=3) -------------------
__global__ void k_im2col(const float* __restrict__ src, float* __restrict__ dst, int Ci) {
    int ci4n = Ci >> 2;
    int total = M_ * 3 * ci4n;
    int i = blockIdx.x * blockDim.x + threadIdx.x;
    if (i >= total) return;
    int ci4 = i % ci4n;
    int tmp = i / ci4n;
    int k = tmp % 3;
    int r = tmp / 3;
    int b = r / T_, t = r % T_;
    int tt = t + k - 1;
    float4 v = make_float4(0.f, 0.f, 0.f, 0.f);
    if (tt >= 0 && tt < T_)
        v = *(const float4*)&src[((size_t)b * T_ + tt) * Ci + ci4 * 4];
    *(float4*)&dst[(size_t)r * 3 * Ci + k * Ci + ci4 * 4] = v;
}

// ------------------- tiled SGEMM: C[M,N] = A[M,K] @ B[K,N] (+bias)(+relu) ----
#define GBM 128
#define GBN 64
#define GBK 16
__global__ void __launch_bounds__(256)
k_gemm(const float* __restrict__ A, const float* __restrict__ Bm,
       const float* __restrict__ bias, float* __restrict__ C,
       int M, int N, int K, int relu)
{
    __shared__ float As[GBK][GBM];
    __shared__ float Bs[GBK][GBN];
    int bm = blockIdx.y * GBM;
    int bn = blockIdx.x * GBN;
    int tid = threadIdx.x;
    int tx = tid & 15;      // col group (4 cols)
    int ty = tid >> 4;      // row group (8 rows)

    float acc[8][4];
#pragma unroll
    for (int j = 0; j < 8; j++)
#pragma unroll
        for (int c = 0; c < 4; c++) acc[j][c] = 0.f;

    for (int k0 = 0; k0 < K; k0 += GBK) {
#pragma unroll
        for (int i = 0; i < 2; i++) {
            int idx = tid + i * 256;            // 0..511
            int row = idx >> 2;                 // 0..127
            int c4 = (idx & 3) * 4;             // 0,4,8,12
            float4 v = *(const float4*)&A[(size_t)(bm + row) * K + k0 + c4];
            As[c4 + 0][row] = v.x;
            As[c4 + 1][row] = v.y;
            As[c4 + 2][row] = v.z;
            As[c4 + 3][row] = v.w;
        }
        {
            int kr = tid >> 4;                  // 0..15
            int n4 = (tid & 15) * 4;            // 0..60
            *(float4*)&Bs[kr][n4] = *(const float4*)&Bm[(size_t)(k0 + kr) * N + bn + n4];
        }
        __syncthreads();
#pragma unroll
        for (int k = 0; k < GBK; k++) {
            float a[8];
            *(float4*)&a[0] = *(const float4*)&As[k][ty * 8];
            *(float4*)&a[4] = *(const float4*)&As[k][ty * 8 + 4];
            float4 bb = *(const float4*)&Bs[k][tx * 4];
#pragma unroll
            for (int j = 0; j < 8; j++) {
                acc[j][0] = fmaf(a[j], bb.x, acc[j][0]);
                acc[j][1] = fmaf(a[j], bb.y, acc[j][1]);
                acc[j][2] = fmaf(a[j], bb.z, acc[j][2]);
                acc[j][3] = fmaf(a[j], bb.w, acc[j][3]);
            }
        }
        __syncthreads();
    }

    float4 bv = make_float4(0.f, 0.f, 0.f, 0.f);
    if (bias) bv = *(const float4*)&bias[bn + tx * 4];
#pragma unroll
    for (int j = 0; j < 8; j++) {
        float4 o;
        o.x = acc[j][0] + bv.x;
        o.y = acc[j][1] + bv.y;
        o.z = acc[j][2] + bv.z;
        o.w = acc[j][3] + bv.w;
        if (relu) {
            o.x = fmaxf(o.x, 0.f); o.y = fmaxf(o.y, 0.f);
            o.z = fmaxf(o.z, 0.f); o.w = fmaxf(o.w, 0.f);
        }
        *(float4*)&C[(size_t)(bm + ty * 8 + j) * N + bn + tx * 4] = o;
    }
}

// ------------------- persistent BiLSTM scan (one layer, both dirs) ----------
// 128 CTAs: dir = bid>>6, 4 hidden units each. Weight-stationary in smem,
// h exchanged via double-buffered global state + software grid barrier.
#define SCAN_NCTA 128
#define SCAN_SMEM ((16*257 + 256*32 + 16*32 + 4*32 + 32) * 4)

__global__ void __launch_bounds__(128, 1)
k_scan(const float* __restrict__ gproj, const float* __restrict__ whh,
       const int* __restrict__ lengths, float* __restrict__ hout)
{
    extern __shared__ float sm[];
    float (*w_s)[257] = (float(*)[257])sm;                         // 16 x 257
    float (*h_s)[32]  = (float(*)[32])(sm + 16 * 257);             // 256 x 32 (k-major)
    float (*g_s)[32]  = (float(*)[32])(sm + 16 * 257 + 256 * 32);  // 16 x 32
    float (*c_s)[32]  = (float(*)[32])(sm + 16 * 257 + 256 * 32 + 16 * 32); // 4 x 32
    int*  L_s = (int*)(sm + 16 * 257 + 256 * 32 + 16 * 32 + 4 * 32);

    const int bid = blockIdx.x;
    const int dir = bid >> 6;
    const int u0  = (bid & 63) * 4;
    const int tid = threadIdx.x;

    // load Whh rows for (gate q, unit j): row = q*256 + u0 + j, local r = q*4+j
    for (int i = tid; i < 16 * 256; i += 128) {
        int rr = i >> 8, k = i & 255;
        int q = rr >> 2, j = rr & 3;
        w_s[rr][k] = whh[(size_t)dir * 262144 + (size_t)(q * 256 + u0 + j) * 256 + k];
    }
    c_s[tid >> 5][tid & 31] = 0.f;
    if (tid < 32) L_s[tid] = lengths[tid];

    const int r   = tid >> 3;        // 0..15 (gate-row within slice)
    const int bq8 = (tid & 7) * 4;   // batch quad
    const int cu  = tid >> 5;        // 0..3  (unit)
    const int cb  = tid & 31;        // 0..31 (batch)
    __syncthreads();

    const unsigned NC = gridDim.x;
    for (int s = 0; s < T_; s++) {
        // A: pull h_prev (other CTAs' results) into smem; bypass L1
        const float* hsrc = g_hstate[s & 1][dir];
        for (int i = tid * 4; i < H_ * B_; i += 128 * 4)
            *(float4*)(&h_s[0][0] + i) = __ldcg((const float4*)(hsrc + i));
        __syncthreads();

        // B: 16 rows x 32 batches of 256-dots; thread: 1 row x 4 batches
        float a0 = 0.f, a1 = 0.f, a2 = 0.f, a3 = 0.f;
        const float* wr = w_s[r];
#pragma unroll 8
        for (int k = 0; k < 256; k++) {
            float w = wr[k];
            float4 h4 = *(const float4*)&h_s[k][bq8];
            a0 = fmaf(w, h4.x, a0);
            a1 = fmaf(w, h4.y, a1);
            a2 = fmaf(w, h4.z, a2);
            a3 = fmaf(w, h4.w, a3);
        }
        g_s[r][bq8 + 0] = a0; g_s[r][bq8 + 1] = a1;
        g_s[r][bq8 + 2] = a2; g_s[r][bq8 + 3] = a3;
        __syncthreads();

        // C: gates + state update; thread: (unit cu, batch cb)
        {
            int L = L_s[cb];
            if (s < L) {
                int t = dir ? (L - 1 - s) : s;
                size_t gb = ((size_t)cb * T_ + t) * N2_ + dir * 1024 + u0 + cu;
                float ig = g_s[0 * 4 + cu][cb] + gproj[gb];
                float fg = g_s[1 * 4 + cu][cb] + gproj[gb + 256];
                float gg = g_s[2 * 4 + cu][cb] + gproj[gb + 512];
                float og = g_s[3 * 4 + cu][cb] + gproj[gb + 768];
                ig = 1.f / (1.f + __expf(-ig));
                fg = 1.f / (1.f + __expf(-fg));
                og = 1.f / (1.f + __expf(-og));
                gg = tanhf(gg);
                float c = fg * c_s[cu][cb] + ig * gg;
                c_s[cu][cb] = c;
                float h = og * tanhf(c);
                g_hstate[(s & 1) ^ 1][dir][(u0 + cu) * 32 + cb] = h;
                hout[((size_t)cb * T_ + t) * D_ + dir * H_ + u0 + cu] = h;
            }
        }

        // D: grid barrier (threadFenceReduction pattern)
        __threadfence();
        __syncthreads();
        if (tid == 0) {
            atomicAdd(&g_bar, 1u);
            unsigned target = (unsigned)(s + 1) * NC;
            while (*((volatile unsigned*)&g_bar) < target) __nanosleep(64);
        }
        __syncthreads();
        __threadfence();
    }
}

// ------------------- pooling + heads -------------------
__global__ void k_pool(const float* __restrict__ hout, const int* __restrict__ len,
                       float* __restrict__ pooled) {
    int b = blockIdx.x;
    int c = blockIdx.y * 128 + threadIdx.x;
    float s = 0.f;
    const float* p = hout + (size_t)b * T_ * D_ + c;
    for (int t = 0; t < T_; t++) s += p[(size_t)t * D_];
    int L = len[b];
    pooled[b * D_ + c] = s / (float)(L > 1 ? L : 1);
}

__global__ void k_utt(const float* __restrict__ pooled, const float* __restrict__ w1t,
                      const float* __restrict__ b1, const float* __restrict__ w2,
                      const float* __restrict__ b2, float* __restrict__ out) {
    int b = blockIdx.x, d = threadIdx.x;
    __shared__ float ps[D_];
    __shared__ float red[D_];
    ps[d] = pooled[b * D_ + d];
    __syncthreads();
    float acc = b1[d];
    for (int k = 0; k < D_; k++) acc = fmaf(ps[k], w1t[k * D_ + d], acc);
    red[d] = fmaxf(acc, 0.f) * w2[d];
    __syncthreads();
    for (int st = 256; st > 0; st >>= 1) {
        if (d < st) red[d] += red[d + st];
        __syncthreads();
    }
    if (d == 0) out[b] = red[0] + b2[0];
}

__global__ void k_seg(const float* __restrict__ hout, const int* __restrict__ segs,
                      const int* __restrict__ len, const int* __restrict__ seglen,
                      const float* __restrict__ w1t, const float* __restrict__ b1,
                      const float* __restrict__ w2, const float* __restrict__ b2,
                      float* __restrict__ out) {
    int si = blockIdx.x, b = blockIdx.y, d = threadIdx.x;
    __shared__ float mean_s[D_];
    __shared__ float red[D_];
    int L = len[b];
    int s0 = segs[(b * S_ + si) * 2 + 0];
    int e0 = segs[(b * S_ + si) * 2 + 1];
    int s = min(max(s0, 0), L);
    int e = max(s + 1, min(e0, L));
    float cnt = (float)(e - s);
    int ec = min(e, T_);
    float acc = 0.f;
    const float* p = hout + ((size_t)b * T_ + s) * D_ + d;
    for (int t = s; t < ec; t++, p += D_) acc += *p;
    mean_s[d] = acc / cnt;
    __syncthreads();
    float hv = b1[d];
    for (int k = 0; k < D_; k++) hv = fmaf(mean_s[k], w1t[k * D_ + d], hv);
    red[d] = fmaxf(hv, 0.f) * w2[d];
    __syncthreads();
    for (int st = 256; st > 0; st >>= 1) {
        if (d < st) red[d] += red[d + st];
        __syncthreads();
    }
    if (d == 0) {
        float sc = red[0] + b2[0];
        out[B_ + b * S_ + si] = (si < seglen[b]) ? sc : 0.f;
    }
}

// ------------------- driver -------------------
extern "C" void kernel_launch(void* const* d_in, const int* in_sizes, int n_in,
                              void* d_out, int out_size) {
    const float* features = (const float*)d_in[0];
    const int*   feat_len = (const int*)d_in[1];
    const int*   segs     = (const int*)d_in[2];
    const int*   seg_len  = (const int*)d_in[3];
    const float* conv1_w  = (const float*)d_in[4];
    const float* conv1_b  = (const float*)d_in[5];
    const float* conv2_w  = (const float*)d_in[6];
    const float* conv2_b  = (const float*)d_in[7];
    const float* wih0     = (const float*)d_in[8];
    const float* whh0     = (const float*)d_in[9];
    const float* bias0    = (const float*)d_in[10];
    const float* wih1     = (const float*)d_in[11];
    const float* whh1     = (const float*)d_in[12];
    const float* bias1    = (const float*)d_in[13];
    const float* seg_w1   = (const float*)d_in[14];
    const float* seg_b1   = (const float*)d_in[15];
    const float* seg_w2   = (const float*)d_in[16];
    const float* seg_b2   = (const float*)d_in[17];
    const float* utt_w1   = (const float*)d_in[18];
    const float* utt_b1   = (const float*)d_in[19];
    const float* utt_w2   = (const float*)d_in[20];
    const float* utt_b2   = (const float*)d_in[21];
    float* out = (float*)d_out;

    static int smem_set = 0;
    cudaFuncSetAttribute(k_scan, cudaFuncAttributeMaxDynamicSharedMemorySize, SCAN_SMEM);
    (void)smem_set;

    float *col, *x1, *x2, *gproj, *hout0, *hout1, *w1t, *w2t, *wih0t, *wih1t,
          *wseg1t, *wutt1t, *pooled;
    cudaGetSymbolAddress((void**)&col,    g_col);
    cudaGetSymbolAddress((void**)&x1,     g_x1);
    cudaGetSymbolAddress((void**)&x2,     g_x2);
    cudaGetSymbolAddress((void**)&gproj,  g_gproj);
    cudaGetSymbolAddress((void**)&hout0,  g_hout0);
    cudaGetSymbolAddress((void**)&hout1,  g_hout1);
    cudaGetSymbolAddress((void**)&w1t,    g_w1t);
    cudaGetSymbolAddress((void**)&w2t,    g_w2t);
    cudaGetSymbolAddress((void**)&wih0t,  g_wih0t);
    cudaGetSymbolAddress((void**)&wih1t,  g_wih1t);
    cudaGetSymbolAddress((void**)&wseg1t, g_wseg1t);
    cudaGetSymbolAddress((void**)&wutt1t, g_wutt1t);
    cudaGetSymbolAddress((void**)&pooled, g_pooled);

    // weight prep
    k_tr_conv<<<(256*80*3 + 255)/256, 256>>>(conv1_w, w1t, 80, 256);
    k_tr_conv<<<(256*256*3 + 255)/256, 256>>>(conv2_w, w2t, 256, 256);
    k_tr_wih<<<(2048*256 + 255)/256, 256>>>(wih0, wih0t, 256);
    k_tr_wih<<<(2048*512 + 255)/256, 256>>>(wih1, wih1t, 512);
    k_tr_sq<<<(D_*D_ + 255)/256, 256>>>(seg_w1, wseg1t);
    k_tr_sq<<<(D_*D_ + 255)/256, 256>>>(utt_w1, wutt1t);

    // zero bilstm outputs (masked positions must be exactly 0)
    k_zero<<<1024, 256>>>(hout0, (size_t)M_ * D_ / 4);
    k_zero<<<1024, 256>>>(hout1, (size_t)M_ * D_ / 4);

    // conv1
    k_im2col<<<(M_*3*20 + 255)/256, 256>>>(features, col, 80);
    k_gemm<<<dim3(256/GBN, M_/GBM), 256>>>(col, w1t, conv1_b, x1, M_, 256, 240, 1);
    // conv2
    k_im2col<<<(M_*3*64 + 255)/256, 256>>>(x1, col, 256);
    k_gemm<<<dim3(256/GBN, M_/GBM), 256>>>(col, w2t, conv2_b, x2, M_, 256, 768, 1);

    // layer 0: input projections (both dirs fused, bias included), then scan
    k_gemm<<<dim3(N2_/GBN, M_/GBM), 256>>>(x2, wih0t, bias0, gproj, M_, N2_, 256, 0);
    k_scan_init<<<32, 256>>>();
    k_scan<<<SCAN_NCTA, 128, SCAN_SMEM>>>(gproj, whh0, feat_len, hout0);

    // layer 1
    k_gemm<<<dim3(N2_/GBN, M_/GBM), 256>>>(hout0, wih1t, bias1, gproj, M_, N2_, 512, 0);
    k_scan_init<<<32, 256>>>();
    k_scan<<<SCAN_NCTA, 128, SCAN_SMEM>>>(gproj, whh1, feat_len, hout1);

    // pooling + heads
    k_pool<<<dim3(B_, 4), 128>>>(hout1, feat_len, pooled);
    k_utt<<<B_, D_>>>(pooled, wutt1t, utt_b1, utt_w2, utt_b2, out);
    k_seg<<<dim3(S_, B_), D_>>>(hout1, segs, feat_len, seg_len,
                                wseg1t, seg_b1, seg_w2, seg_b2, out);
}

// round 3
// speedup vs baseline: 1.3245x; 1.3245x over previous
#include <cuda_runtime.h>
#include <cuda_bf16.h>

#define B_    32
#define T_    2000
#define F_    80
#define H_    256
#define S_    100
#define D_    512        // 2*H
#define M_    (B_*T_)    // 64000
#define N2_   2048       // 2 dirs * 4H

typedef unsigned long long ull;

// ------------------- packed f32x2 helpers (FFMA2) -------------------
__device__ __forceinline__ ull pack2(float x, float y) {
    ull r; asm("mov.b64 %0, {%1, %2};" : "=l"(r) : "f"(x), "f"(y)); return r;
}
__device__ __forceinline__ float2 unpack2(ull v) {
    float2 r; asm("mov.b64 {%0, %1}, %2;" : "=f"(r.x), "=f"(r.y) : "l"(v)); return r;
}
__device__ __forceinline__ void fma2(ull& d, ull a, ull b) {
    asm("fma.rn.f32x2 %0, %1, %2, %0;" : "+l"(d) : "l"(a), "l"(b));
}
__device__ __forceinline__ float tanh_fast(float x) {
    float e = __expf(2.f * x);
    return 1.f - 2.f / (e + 1.f);
}

// ------------------- scratch (static __device__, no allocs) -------------------
__device__ float g_col[(size_t)M_*768];          // im2col buffer (reused)
__device__ float g_x1 [(size_t)M_*256];          // conv1 out
__device__ float g_x2 [(size_t)M_*256];          // conv2 out
__device__ float g_gproj[(size_t)M_*N2_];        // input projections (reused L0/L1)
__device__ float g_hout0[(size_t)M_*D_];         // layer0 bilstm out
__device__ float g_hout1[(size_t)M_*D_];         // layer1 bilstm out
__device__ float g_w1t [240*256];
__device__ float g_w2t [768*256];
__device__ float g_wih0t[256*N2_];
__device__ float g_wih1t[512*N2_];
__device__ float g_wseg1t[D_*D_];
__device__ float g_wutt1t[D_*D_];
__device__ float g_pooled[B_*D_];
__device__ float g_hstate[2][2][H_*B_];          // [buf][dir][k*32+b]
__device__ unsigned g_bar;

// ------------------- small prep kernels -------------------
__global__ void k_tr_conv(const float* __restrict__ w, float* __restrict__ wt,
                          int Ci, int Co) {
    int i = blockIdx.x * blockDim.x + threadIdx.x;
    int tot = Co * Ci * 3;
    if (i < tot) {
        int k = i % 3;
        int ci = (i / 3) % Ci;
        int co = i / (3 * Ci);
        wt[(k * Ci + ci) * Co + co] = w[i];
    }
}

__global__ void k_tr_wih(const float* __restrict__ w, float* __restrict__ wt, int K) {
    int i = blockIdx.x * blockDim.x + threadIdx.x;   // i = dr*K + k
    int tot = 2048 * K;
    if (i < tot) {
        int k  = i % K;
        int dr = i / K;        // d*1024 + r
        wt[(size_t)k * 2048 + dr] = w[i];
    }
}

__global__ void k_tr_sq(const float* __restrict__ w, float* __restrict__ wt) {
    int i = blockIdx.x * blockDim.x + threadIdx.x;   // over 512*512
    if (i < D_ * D_) {
        int d = i / D_, k = i % D_;
        wt[k * D_ + d] = w[i];
    }
}

__global__ void k_zero(float* __restrict__ p, size_t n4) {
    size_t i = (size_t)blockIdx.x * blockDim.x + threadIdx.x;
    size_t stride = (size_t)gridDim.x * blockDim.x;
    float4 z = make_float4(0.f, 0.f, 0.f, 0.f);
    for (; i < n4; i += stride) ((float4*)p)[i] = z;
}

__global__ void k_scan_init() {
    int i = blockIdx.x * blockDim.x + threadIdx.x;
    if (i == 0) g_bar = 0u;
    float* p = &g_hstate[0][0][0];
    for (int j = i; j < 2 * 2 * H_ * B_; j += gridDim.x * blockDim.x) p[j] = 0.f;
}

// ------------------- im2col (pad=1, kernel=3) -------------------
__global__ void k_im2col(const float* __restrict__ src, float* __restrict__ dst, int Ci) {
    int ci4n = Ci >> 2;
    int total = M_ * 3 * ci4n;
    int i = blockIdx.x * blockDim.x + threadIdx.x;
    if (i >= total) return;
    int ci4 = i % ci4n;
    int tmp = i / ci4n;
    int k = tmp % 3;
    int r = tmp / 3;
    int b = r / T_, t = r % T_;
    int tt = t + k - 1;
    float4 v = make_float4(0.f, 0.f, 0.f, 0.f);
    if (tt >= 0 && tt < T_)
        v = *(const float4*)&src[((size_t)b * T_ + tt) * Ci + ci4 * 4];
    *(float4*)&dst[(size_t)r * 3 * Ci + k * Ci + ci4 * 4] = v;
}

// ---- tiled SGEMM (packed f32x2): C[M,N] = A[M,K] @ B[K,N] (+bias)(+relu) ----
#define GBM 128
#define GBN 128
#define GBK 16
__global__ void __launch_bounds__(256, 2)
k_gemm(const float* __restrict__ A, const float* __restrict__ Bm,
       const float* __restrict__ bias, float* __restrict__ C,
       int M, int N, int K, int relu)
{
    __shared__ float As[GBK][132];
    __shared__ float Bs[GBK][132];
    int bm = blockIdx.y * GBM;
    int bn = blockIdx.x * GBN;
    int tid = threadIdx.x;
    int tr = tid >> 4;      // 0..15: rows tr*8..+7
    int tc = tid & 15;      // 0..15: cols tc*8..+7

    ull acc[4][8];
#pragma unroll
    for (int i = 0; i < 4; i++)
#pragma unroll
        for (int j = 0; j < 8; j++) acc[i][j] = 0ull;

    for (int k0 = 0; k0 < K; k0 += GBK) {
#pragma unroll
        for (int i = 0; i < 2; i++) {
            int idx = tid + i * 256;            // 0..511
            int row = idx >> 2;                 // 0..127
            int c4 = (idx & 3) * 4;             // 0,4,8,12
            float4 v = *(const float4*)&A[(size_t)(bm + row) * K + k0 + c4];
            As[c4 + 0][row] = v.x;
            As[c4 + 1][row] = v.y;
            As[c4 + 2][row] = v.z;
            As[c4 + 3][row] = v.w;
        }
#pragma unroll
        for (int i = 0; i < 2; i++) {
            int idx = tid + i * 256;
            int kr = idx >> 5;                  // 0..15
            int n4 = (idx & 31) * 4;            // 0..124
            *(float4*)&Bs[kr][n4] = *(const float4*)&Bm[(size_t)(k0 + kr) * N + bn + n4];
        }
        __syncthreads();
#pragma unroll
        for (int k = 0; k < GBK; k++) {
            ulonglong2 a0 = *(const ulonglong2*)&As[k][tr * 8];
            ulonglong2 a1 = *(const ulonglong2*)&As[k][tr * 8 + 4];
            float4 b0 = *(const float4*)&Bs[k][tc * 8];
            float4 b1 = *(const float4*)&Bs[k][tc * 8 + 4];
            ull ar0 = a0.x, ar1 = a0.y, ar2 = a1.x, ar3 = a1.y;
            ull bd0 = pack2(b0.x, b0.x), bd1 = pack2(b0.y, b0.y);
            ull bd2 = pack2(b0.z, b0.z), bd3 = pack2(b0.w, b0.w);
            ull bd4 = pack2(b1.x, b1.x), bd5 = pack2(b1.y, b1.y);
            ull bd6 = pack2(b1.z, b1.z), bd7 = pack2(b1.w, b1.w);
            fma2(acc[0][0], ar0, bd0); fma2(acc[0][1], ar0, bd1);
            fma2(acc[0][2], ar0, bd2); fma2(acc[0][3], ar0, bd3);
            fma2(acc[0][4], ar0, bd4); fma2(acc[0][5], ar0, bd5);
            fma2(acc[0][6], ar0, bd6); fma2(acc[0][7], ar0, bd7);
            fma2(acc[1][0], ar1, bd0); fma2(acc[1][1], ar1, bd1);
            fma2(acc[1][2], ar1, bd2); fma2(acc[1][3], ar1, bd3);
            fma2(acc[1][4], ar1, bd4); fma2(acc[1][5], ar1, bd5);
            fma2(acc[1][6], ar1, bd6); fma2(acc[1][7], ar1, bd7);
            fma2(acc[2][0], ar2, bd0); fma2(acc[2][1], ar2, bd1);
            fma2(acc[2][2], ar2, bd2); fma2(acc[2][3], ar2, bd3);
            fma2(acc[2][4], ar2, bd4); fma2(acc[2][5], ar2, bd5);
            fma2(acc[2][6], ar2, bd6); fma2(acc[2][7], ar2, bd7);
            fma2(acc[3][0], ar3, bd0); fma2(acc[3][1], ar3, bd1);
            fma2(acc[3][2], ar3, bd2); fma2(acc[3][3], ar3, bd3);
            fma2(acc[3][4], ar3, bd4); fma2(acc[3][5], ar3, bd5);
            fma2(acc[3][6], ar3, bd6); fma2(acc[3][7], ar3, bd7);
        }
        __syncthreads();
    }

    float bb[8];
    if (bias) {
        float4 bv0 = *(const float4*)&bias[bn + tc * 8];
        float4 bv1 = *(const float4*)&bias[bn + tc * 8 + 4];
        bb[0] = bv0.x; bb[1] = bv0.y; bb[2] = bv0.z; bb[3] = bv0.w;
        bb[4] = bv1.x; bb[5] = bv1.y; bb[6] = bv1.z; bb[7] = bv1.w;
    } else {
#pragma unroll
        for (int c = 0; c < 8; c++) bb[c] = 0.f;
    }
#pragma unroll
    for (int rp = 0; rp < 4; rp++) {
        float o0[8], o1[8];
#pragma unroll
        for (int c = 0; c < 8; c++) {
            float2 u = unpack2(acc[rp][c]);
            o0[c] = u.x + bb[c];
            o1[c] = u.y + bb[c];
            if (relu) { o0[c] = fmaxf(o0[c], 0.f); o1[c] = fmaxf(o1[c], 0.f); }
        }
        int row0 = bm + tr * 8 + rp * 2;
        float* p0 = &C[(size_t)row0 * N + bn + tc * 8];
        float* p1 = p0 + N;
        *(float4*)p0       = make_float4(o0[0], o0[1], o0[2], o0[3]);
        *(float4*)(p0 + 4) = make_float4(o0[4], o0[5], o0[6], o0[7]);
        *(float4*)p1       = make_float4(o1[0], o1[1], o1[2], o1[3]);
        *(float4*)(p1 + 4) = make_float4(o1[4], o1[5], o1[6], o1[7]);
    }
}

// ------------------- persistent BiLSTM scan (one layer, both dirs) ----------
// 128 CTAs: dir = bid>>6, 4 hidden units each. Weights duplicated as (w,w)
// u64 pairs in smem so the recurrent dot is pure FFMA2; 2-way k-split across
// the 128 threads; h exchanged via double-buffered global + sw grid barrier.
#define SCAN_NCTA 128
#define SCAN_SMEM ((8192 + 8192 + 1024 + 128 + 32) * 4)

__global__ void __launch_bounds__(128, 1)
k_scan(const float* __restrict__ gproj, const float* __restrict__ whh,
       const int* __restrict__ lengths, float* __restrict__ hout)
{
    extern __shared__ float sm[];
    ull*   w2  = (ull*)sm;                 // [256][16] dup'd weights (32 KB)
    float* h_s = sm + 8192;                // [256][32] h (k-major, 32 KB)
    float* g_p = sm + 16384;               // [2][16][32] partial gates (4 KB)
    float* c_s = sm + 17408;               // [4][32] cell state
    int*   L_s = (int*)(sm + 17536);       // [32]

    const int bid = blockIdx.x;
    const int dir = bid >> 6;
    const int u0  = (bid & 63) * 4;
    const int tid = threadIdx.x;

    // weights: local row r = q*4+j  <->  whh row q*256+u0+j; store dup'd (w,w)
    for (int i = tid; i < 4096; i += 128) {
        int k = i >> 4, r = i & 15;
        int q = r >> 2, j = r & 3;
        float w = whh[(size_t)dir * 262144 + (size_t)(q * 256 + u0 + j) * 256 + k];
        w2[(size_t)k * 16 + r] = pack2(w, w);
    }
    c_s[tid] = 0.f;
    if (tid < 32) L_s[tid] = lengths[tid];
    __syncthreads();

    const int kh = tid >> 6;             // k-half 0/1
    const int rp = (tid & 63) >> 3;      // row pair 0..7 (rows 2rp, 2rp+1)
    const int b4 = tid & 7;              // batch quad 0..7
    const int cu = tid >> 5;             // 0..3 (unit) for gate phase
    const int cb = tid & 31;             // 0..31 (batch)
    const int Lcb = L_s[cb];

    for (int s = 0; s < T_; s++) {
        // prefetch gproj gates (independent of h; hides DRAM latency)
        bool act = s < Lcb;
        int t = dir ? (Lcb - 1 - s) : s;
        if (!act) t = 0;
        size_t gb = ((size_t)cb * T_ + t) * N2_ + (size_t)dir * 1024 + u0 + cu;
        float pi = __ldcg(gproj + gb);
        float pf = __ldcg(gproj + gb + 256);
        float pg = __ldcg(gproj + gb + 512);
        float po = __ldcg(gproj + gb + 768);

        // pull h_prev into smem (L1-bypass; other CTAs produced it)
        const float* hsrc = g_hstate[s & 1][dir];
#pragma unroll
        for (int i = 0; i < 16; i++) {
            int idx = (tid + i * 128) * 4;
            *(float4*)(h_s + idx) = __ldcg((const float4*)(hsrc + idx));
        }
        __syncthreads();

        // dot: rows (2rp,2rp+1) x batches (4b4..+3) over k-half, all FFMA2
        ull a00 = 0ull, a01 = 0ull, a10 = 0ull, a11 = 0ull;
        const ull*   wp = w2 + (size_t)(kh * 128) * 16 + rp * 2;
        const float* hp = h_s + (kh * 128) * 32 + b4 * 4;
#pragma unroll 4
        for (int k = 0; k < 128; k++) {
            ulonglong2 w = *(const ulonglong2*)wp;
            ulonglong2 h = *(const ulonglong2*)hp;
            fma2(a00, w.x, h.x); fma2(a01, w.x, h.y);
            fma2(a10, w.y, h.x); fma2(a11, w.y, h.y);
            wp += 16; hp += 32;
        }
        {
            float* gp0 = g_p + kh * 512 + (rp * 2) * 32 + b4 * 4;
            float2 u;
            u = unpack2(a00); gp0[0] = u.x; gp0[1] = u.y;
            u = unpack2(a01); gp0[2] = u.x; gp0[3] = u.y;
            float* gp1 = gp0 + 32;
            u = unpack2(a10); gp1[0] = u.x; gp1[1] = u.y;
            u = unpack2(a11); gp1[2] = u.x; gp1[3] = u.y;
        }
        __syncthreads();

        // gates + state update; thread: (unit cu, batch cb)
        if (act) {
            float gi = g_p[(cu)      * 32 + cb] + g_p[512 + (cu)      * 32 + cb] + pi;
            float gf = g_p[(4 + cu)  * 32 + cb] + g_p[512 + (4 + cu)  * 32 + cb] + pf;
            float gg = g_p[(8 + cu)  * 32 + cb] + g_p[512 + (8 + cu)  * 32 + cb] + pg;
            float go = g_p[(12 + cu) * 32 + cb] + g_p[512 + (12 + cu) * 32 + cb] + po;
            gi = 1.f / (1.f + __expf(-gi));
            gf = 1.f / (1.f + __expf(-gf));
            go = 1.f / (1.f + __expf(-go));
            gg = tanh_fast(gg);
            float c = gf * c_s[cu * 32 + cb] + gi * gg;
            c_s[cu * 32 + cb] = c;
            float h = go * tanh_fast(c);
            g_hstate[(s & 1) ^ 1][dir][(u0 + cu) * 32 + cb] = h;
            hout[((size_t)cb * T_ + t) * D_ + dir * H_ + u0 + cu] = h;
        }

        // grid barrier
        __threadfence();
        __syncthreads();
        if (tid == 0) {
            atomicAdd(&g_bar, 1u);
            unsigned target = (unsigned)(s + 1) * (unsigned)SCAN_NCTA;
            while (*((volatile unsigned*)&g_bar) < target) __nanosleep(32);
        }
        __syncthreads();
    }
}

// ------------------- pooling + heads -------------------
__global__ void k_pool(const float* __restrict__ hout, const int* __restrict__ len,
                       float* __restrict__ pooled) {
    int b = blockIdx.x;
    int c = blockIdx.y * 128 + threadIdx.x;
    float s = 0.f;
    const float* p = hout + (size_t)b * T_ * D_ + c;
    for (int t = 0; t < T_; t++) s += p[(size_t)t * D_];
    int L = len[b];
    pooled[b * D_ + c] = s / (float)(L > 1 ? L : 1);
}

__global__ void k_utt(const float* __restrict__ pooled, const float* __restrict__ w1t,
                      const float* __restrict__ b1, const float* __restrict__ w2,
                      const float* __restrict__ b2, float* __restrict__ out) {
    int b = blockIdx.x, d = threadIdx.x;
    __shared__ float ps[D_];
    __shared__ float red[D_];
    ps[d] = pooled[b * D_ + d];
    __syncthreads();
    float acc = b1[d];
    for (int k = 0; k < D_; k++) acc = fmaf(ps[k], w1t[k * D_ + d], acc);
    red[d] = fmaxf(acc, 0.f) * w2[d];
    __syncthreads();
    for (int st = 256; st > 0; st >>= 1) {
        if (d < st) red[d] += red[d + st];
        __syncthreads();
    }
    if (d == 0) out[b] = red[0] + b2[0];
}

__global__ void k_seg(const float* __restrict__ hout, const int* __restrict__ segs,
                      const int* __restrict__ len, const int* __restrict__ seglen,
                      const float* __restrict__ w1t, const float* __restrict__ b1,
                      const float* __restrict__ w2, const float* __restrict__ b2,
                      float* __restrict__ out) {
    int si = blockIdx.x, b = blockIdx.y, d = threadIdx.x;
    __shared__ float mean_s[D_];
    __shared__ float red[D_];
    int L = len[b];
    int s0 = segs[(b * S_ + si) * 2 + 0];
    int e0 = segs[(b * S_ + si) * 2 + 1];
    int s = min(max(s0, 0), L);
    int e = max(s + 1, min(e0, L));
    float cnt = (float)(e - s);
    int ec = min(e, T_);
    float acc = 0.f;
    const float* p = hout + ((size_t)b * T_ + s) * D_ + d;
    for (int t = s; t < ec; t++, p += D_) acc += *p;
    mean_s[d] = acc / cnt;
    __syncthreads();
    float hv = b1[d];
    for (int k = 0; k < D_; k++) hv = fmaf(mean_s[k], w1t[k * D_ + d], hv);
    red[d] = fmaxf(hv, 0.f) * w2[d];
    __syncthreads();
    for (int st = 256; st > 0; st >>= 1) {
        if (d < st) red[d] += red[d + st];
        __syncthreads();
    }
    if (d == 0) {
        float sc = red[0] + b2[0];
        out[B_ + b * S_ + si] = (si < seglen[b]) ? sc : 0.f;
    }
}

// ------------------- driver -------------------
extern "C" void kernel_launch(void* const* d_in, const int* in_sizes, int n_in,
                              void* d_out, int out_size) {
    const float* features = (const float*)d_in[0];
    const int*   feat_len = (const int*)d_in[1];
    const int*   segs     = (const int*)d_in[2];
    const int*   seg_len  = (const int*)d_in[3];
    const float* conv1_w  = (const float*)d_in[4];
    const float* conv1_b  = (const float*)d_in[5];
    const float* conv2_w  = (const float*)d_in[6];
    const float* conv2_b  = (const float*)d_in[7];
    const float* wih0     = (const float*)d_in[8];
    const float* whh0     = (const float*)d_in[9];
    const float* bias0    = (const float*)d_in[10];
    const float* wih1     = (const float*)d_in[11];
    const float* whh1     = (const float*)d_in[12];
    const float* bias1    = (const float*)d_in[13];
    const float* seg_w1   = (const float*)d_in[14];
    const float* seg_b1   = (const float*)d_in[15];
    const float* seg_w2   = (const float*)d_in[16];
    const float* seg_b2   = (const float*)d_in[17];
    const float* utt_w1   = (const float*)d_in[18];
    const float* utt_b1   = (const float*)d_in[19];
    const float* utt_w2   = (const float*)d_in[20];
    const float* utt_b2   = (const float*)d_in[21];
    float* out = (float*)d_out;

    cudaFuncSetAttribute(k_scan, cudaFuncAttributeMaxDynamicSharedMemorySize, SCAN_SMEM);

    float *col, *x1, *x2, *gproj, *hout0, *hout1, *w1t, *w2t, *wih0t, *wih1t,
          *wseg1t, *wutt1t, *pooled;
    cudaGetSymbolAddress((void**)&col,    g_col);
    cudaGetSymbolAddress((void**)&x1,     g_x1);
    cudaGetSymbolAddress((void**)&x2,     g_x2);
    cudaGetSymbolAddress((void**)&gproj,  g_gproj);
    cudaGetSymbolAddress((void**)&hout0,  g_hout0);
    cudaGetSymbolAddress((void**)&hout1,  g_hout1);
    cudaGetSymbolAddress((void**)&w1t,    g_w1t);
    cudaGetSymbolAddress((void**)&w2t,    g_w2t);
    cudaGetSymbolAddress((void**)&wih0t,  g_wih0t);
    cudaGetSymbolAddress((void**)&wih1t,  g_wih1t);
    cudaGetSymbolAddress((void**)&wseg1t, g_wseg1t);
    cudaGetSymbolAddress((void**)&wutt1t, g_wutt1t);
    cudaGetSymbolAddress((void**)&pooled, g_pooled);

    // conv1 (launches 1-3)
    k_tr_conv<<<(256*80*3 + 255)/256, 256>>>(conv1_w, w1t, 80, 256);
    k_im2col<<<(M_*3*20 + 255)/256, 256>>>(features, col, 80);
    k_gemm<<<dim3(256/GBN, M_/GBM), 256>>>(col, w1t, conv1_b, x1, M_, 256, 240, 1);
    // conv2 (launches 4-6; launch #6 is the profiled GEMM)
    k_tr_conv<<<(256*256*3 + 255)/256, 256>>>(conv2_w, w2t, 256, 256);
    k_im2col<<<(M_*3*64 + 255)/256, 256>>>(x1, col, 256);
    k_gemm<<<dim3(256/GBN, M_/GBM), 256>>>(col, w2t, conv2_b, x2, M_, 256, 768, 1);

    // layer 0: input projections (both dirs fused, bias included), then scan
    k_tr_wih<<<(2048*256 + 255)/256, 256>>>(wih0, wih0t, 256);
    k_gemm<<<dim3(N2_/GBN, M_/GBM), 256>>>(x2, wih0t, bias0, gproj, M_, N2_, 256, 0);
    k_zero<<<1024, 256>>>(hout0, (size_t)M_ * D_ / 4);
    k_scan_init<<<32, 256>>>();
    k_scan<<<SCAN_NCTA, 128, SCAN_SMEM>>>(gproj, whh0, feat_len, hout0);

    // layer 1
    k_tr_wih<<<(2048*512 + 255)/256, 256>>>(wih1, wih1t, 512);
    k_gemm<<<dim3(N2_/GBN, M_/GBM), 256>>>(hout0, wih1t, bias1, gproj, M_, N2_, 512, 0);
    k_zero<<<1024, 256>>>(hout1, (size_t)M_ * D_ / 4);
    k_scan_init<<<32, 256>>>();
    k_scan<<<SCAN_NCTA, 128, SCAN_SMEM>>>(gproj, whh1, feat_len, hout1);

    // pooling + heads
    k_tr_sq<<<(D_*D_ + 255)/256, 256>>>(seg_w1, wseg1t);
    k_tr_sq<<<(D_*D_ + 255)/256, 256>>>(utt_w1, wutt1t);
    k_pool<<<dim3(B_, 4), 128>>>(hout1, feat_len, pooled);
    k_utt<<<B_, D_>>>(pooled, wutt1t, utt_b1, utt_w2, utt_b2, out);
    k_seg<<<dim3(S_, B_), D_>>>(hout1, segs, feat_len, seg_len,
                                wseg1t, seg_b1, seg_w2, seg_b2, out);
}